// round 6
// baseline (speedup 1.0000x reference)
#include <cuda_runtime.h>
#include <cuda_bf16.h>

// ---------------- problem constants ----------------
// x: (32, 128, 128, 80) fp32; C=80, NH=8, DH=10, WIN=GRID=8 -> 64-token windows
// windows per stage: 32 * 16 * 16 = 8192 ; tokens total 524288

#define TOK_TOTAL (32*128*128)

__device__ float g_buf1[(size_t)TOK_TOTAL * 80];
__device__ float g_buf2[(size_t)TOK_TOTAL * 80];

// ---------------- bf16 mma helpers (fragment conventions validated R3/R4) ----
__device__ __forceinline__ unsigned pack2(float lo, float hi) {
    __nv_bfloat162 t = __floats2bfloat162_rn(lo, hi);
    return *reinterpret_cast<unsigned*>(&t);
}

__device__ __forceinline__ void mma_bf16(float* c, const unsigned* a, unsigned b0, unsigned b1) {
    asm volatile(
        "mma.sync.aligned.m16n8k16.row.col.f32.bf16.bf16.f32 "
        "{%0,%1,%2,%3}, {%4,%5,%6,%7}, {%8,%9}, {%0,%1,%2,%3};\n"
        : "+f"(c[0]), "+f"(c[1]), "+f"(c[2]), "+f"(c[3])
        : "r"(a[0]), "r"(a[1]), "r"(a[2]), "r"(a[3]), "r"(b0), "r"(b1));
}

// =====================================================================
// Fused window attention via bf16 mma, 512 threads = 16 warps.
// 4 windows per CTA; weights staged (transposed bf16, n-padded) once.
//
// smem layout (bytes):
//   sWqkvT [256][88] bf16 @      0  (45056)  rows 240..255 zero
//   sWprojT [96][88] bf16 @  45056  (16896)  rows 80..95 zero
//   sXN    [64][81] f32   @  61952  (20736)  fp32 residual
//   sXNh   [64][88] bf16  @  82688  (11264)  A panel
//   sQ   [8][64][18] bf16 @  93952  (18432)  per-head Q (k pad 10->16, scaled)
//   sK   [8][64][18] bf16 @ 112384  (18432)
//   sVT  [8][16][72] bf16 @ 130816  (18432)  per-head V^T (PV B-op)
//   sO     [64][88] bf16  @ 149248  (11264)  attn out, A panel for proj
//   sBqkv  [240] f32      @ 160512
//   sBproj [80]  f32      @ 161472
// total 161792 B
// =====================================================================
constexpr int ATTN_SMEM_BYTES = 161792;
constexpr int ATTN_TILES_PER_CTA = 4;
constexpr int ATTN_NCTA = 8192 / ATTN_TILES_PER_CTA;   // 2048
constexpr float QK_SCALE = 0.31622776601683794f;       // DH^-0.5

template<bool IS_GRID>
__global__ void __launch_bounds__(512, 1)
attn_kernel(const float* __restrict__ x, float* __restrict__ y,
            const float* __restrict__ wqkv, const float* __restrict__ bqkv,
            const float* __restrict__ wproj, const float* __restrict__ bproj)
{
    extern __shared__ float smf[];
    char* smb = reinterpret_cast<char*>(smf);
    __nv_bfloat16* sWqkvT  = reinterpret_cast<__nv_bfloat16*>(smb);           // [256][88]
    __nv_bfloat16* sWprojT = reinterpret_cast<__nv_bfloat16*>(smb + 45056);   // [96][88]
    float*         sXN     = reinterpret_cast<float*>(smb + 61952);           // [64][81]
    __nv_bfloat16* sXNh    = reinterpret_cast<__nv_bfloat16*>(smb + 82688);   // [64][88]
    __nv_bfloat16* sQ      = reinterpret_cast<__nv_bfloat16*>(smb + 93952);   // [8][64][18]
    __nv_bfloat16* sK      = reinterpret_cast<__nv_bfloat16*>(smb + 112384);  // [8][64][18]
    __nv_bfloat16* sVT     = reinterpret_cast<__nv_bfloat16*>(smb + 130816);  // [8][16][72]
    __nv_bfloat16* sO      = reinterpret_cast<__nv_bfloat16*>(smb + 149248);  // [64][88]
    float*         sBqkv   = reinterpret_cast<float*>(smb + 160512);          // [240]
    float*         sBproj  = reinterpret_cast<float*>(smb + 161472);          // [80]

    const int tid  = threadIdx.x;
    const int w    = tid >> 5, lane = tid & 31;
    const int g    = lane >> 2, tq  = lane & 3;

    // ---- one-time: weights transposed->bf16, pads zeroed, biases ----
    for (int idx = tid; idx < 19200; idx += 512) {
        int k = idx / 240, n = idx % 240;
        sWqkvT[n*88 + k] = __float2bfloat16(wqkv[idx]);
    }
    for (int idx = tid; idx < 6400; idx += 512) {
        int k = idx / 80, n = idx % 80;
        sWprojT[n*88 + k] = __float2bfloat16(wproj[idx]);
    }
    for (int i = tid; i < 704; i += 512)
        reinterpret_cast<unsigned*>(sWqkvT + 240*88)[i] = 0u;   // pad rows 240..255
    for (int i = tid; i < 704; i += 512)
        reinterpret_cast<unsigned*>(sWprojT + 80*88)[i] = 0u;   // pad rows 80..95
    if (tid < 240) sBqkv[tid] = bqkv[tid];
    if (tid < 80)  sBproj[tid] = bproj[tid];
    // zero k-pads d=10..17 of sQ and sK (stay zero across tiles)
    for (int i = tid; i < 2048; i += 512) {
        int row = i >> 2, p = i & 3;
        reinterpret_cast<unsigned*>(sQ + row*18 + 10)[p] = 0u;
        reinterpret_cast<unsigned*>(sK + row*18 + 10)[p] = 0u;
    }

    for (int it = 0; it < ATTN_TILES_PER_CTA; it++) {
        const int wIdx = blockIdx.x * ATTN_TILES_PER_CTA + it;
        const int bb  = wIdx >> 8;
        const int rem = wIdx & 255;
        const int wh  = rem >> 4, ww = rem & 15;

        // ---- load + l2norm: 8 threads per token (float2) ----
        {
            const int t = tid >> 3, lg = tid & 7;
            const int ti = t >> 3, tj = t & 7;
            int pr, pc;
            if (IS_GRID) { pr = ti*16 + wh; pc = tj*16 + ww; }
            else         { pr = wh*8 + ti;  pc = ww*8 + tj;  }
            const long pix = ((long)bb*128 + pr)*128 + pc;
            const float2* xr = reinterpret_cast<const float2*>(x + pix*80) + lg*5;
            float v[10]; float ss = 0.f;
            #pragma unroll
            for (int u = 0; u < 5; u++) {
                float2 f = xr[u];
                v[2*u]=f.x; v[2*u+1]=f.y;
                ss += f.x*f.x + f.y*f.y;
            }
            ss += __shfl_xor_sync(0xffffffffu, ss, 1);
            ss += __shfl_xor_sync(0xffffffffu, ss, 2);
            ss += __shfl_xor_sync(0xffffffffu, ss, 4);
            const float inv = rsqrtf(fmaxf(ss, 1e-24f));
            float* xn = sXN + t*81 + lg*10;
            unsigned* xh = reinterpret_cast<unsigned*>(sXNh + t*88 + lg*10);
            #pragma unroll
            for (int u = 0; u < 10; u++) { v[u] *= inv; xn[u] = v[u]; }
            #pragma unroll
            for (int u = 0; u < 5; u++) xh[u] = pack2(v[2*u], v[2*u+1]);
        }
        __syncthreads();   // (covers one-time staging before first tile)

        // ---- QKV GEMM: 16 warps = 4 mt x 4 j-groups of 8 ntiles ----
        {
            const int mt    = w & 3;
            const int jbase = (w >> 2) * 8;
            float acc[8][4];
            #pragma unroll
            for (int j = 0; j < 8; j++)
                #pragma unroll
                for (int e = 0; e < 4; e++) acc[j][e] = 0.f;

            #pragma unroll
            for (int ks = 0; ks < 5; ks++) {
                unsigned a[4];
                const __nv_bfloat16* ap = sXNh + (mt*16 + g)*88 + ks*16;
                a[0] = *reinterpret_cast<const unsigned*>(ap + 2*tq);
                a[1] = *reinterpret_cast<const unsigned*>(ap + 8*88 + 2*tq);
                a[2] = *reinterpret_cast<const unsigned*>(ap + 2*tq + 8);
                a[3] = *reinterpret_cast<const unsigned*>(ap + 8*88 + 2*tq + 8);
                #pragma unroll
                for (int j = 0; j < 8; j++) {
                    const __nv_bfloat16* bp = sWqkvT + ((jbase+j)*8 + g)*88 + ks*16;
                    unsigned b0 = *reinterpret_cast<const unsigned*>(bp + 2*tq);
                    unsigned b1 = *reinterpret_cast<const unsigned*>(bp + 2*tq + 8);
                    mma_bf16(acc[j], a, b0, b1);
                }
            }
            const int rowA = mt*16 + g;
            #pragma unroll
            for (int j = 0; j < 8; j++) {
                #pragma unroll
                for (int e = 0; e < 2; e++) {
                    const int col = (jbase+j)*8 + 2*tq + e;
                    if (col < 240) {
                        const int h = col / 30;
                        const int r = col - h*30;
                        const int d = (r >= 20) ? r - 20 : (r >= 10 ? r - 10 : r);
                        const float bias = sBqkv[col];
                        float vA = acc[j][e]   + bias;
                        float vB = acc[j][2+e] + bias;
                        if (r < 10) {
                            sQ[h*1152 + rowA*18 + d]     = __float2bfloat16(vA * QK_SCALE);
                            sQ[h*1152 + (rowA+8)*18 + d] = __float2bfloat16(vB * QK_SCALE);
                        } else if (r < 20) {
                            sK[h*1152 + rowA*18 + d]     = __float2bfloat16(vA);
                            sK[h*1152 + (rowA+8)*18 + d] = __float2bfloat16(vB);
                        } else {
                            sVT[h*1152 + d*72 + rowA]     = __float2bfloat16(vA);
                            sVT[h*1152 + d*72 + rowA + 8] = __float2bfloat16(vB);
                        }
                    }
                }
            }
        }
        __syncthreads();

        // ---- attention: 16 warps = 8 heads x 2 m-passes ----
        {
            const int h    = w & 7;
            const int pass = w >> 3;
            const __nv_bfloat16* Qh = sQ  + h*1152;
            const __nv_bfloat16* Kh = sK  + h*1152;
            const __nv_bfloat16* Vh = sVT + h*1152;

            float s[2][8][4];
            unsigned qa[2][4];
            #pragma unroll
            for (int mi = 0; mi < 2; mi++) {
                const __nv_bfloat16* qp = Qh + ((pass*2+mi)*16 + g)*18;
                qa[mi][0] = *reinterpret_cast<const unsigned*>(qp + 2*tq);
                qa[mi][1] = *reinterpret_cast<const unsigned*>(qp + 8*18 + 2*tq);
                qa[mi][2] = *reinterpret_cast<const unsigned*>(qp + 2*tq + 8);
                qa[mi][3] = *reinterpret_cast<const unsigned*>(qp + 8*18 + 2*tq + 8);
            }
            #pragma unroll
            for (int nt = 0; nt < 8; nt++) {
                const __nv_bfloat16* kp = Kh + (nt*8 + g)*18;
                unsigned b0 = *reinterpret_cast<const unsigned*>(kp + 2*tq);
                unsigned b1 = *reinterpret_cast<const unsigned*>(kp + 2*tq + 8);
                #pragma unroll
                for (int mi = 0; mi < 2; mi++) {
                    #pragma unroll
                    for (int e = 0; e < 4; e++) s[mi][nt][e] = 0.f;
                    mma_bf16(s[mi][nt], qa[mi], b0, b1);
                }
            }
            float invA[2], invB[2];
            #pragma unroll
            for (int mi = 0; mi < 2; mi++) {
                float mA = -1e30f, mB = -1e30f;
                #pragma unroll
                for (int nt = 0; nt < 8; nt++) {
                    mA = fmaxf(mA, fmaxf(s[mi][nt][0], s[mi][nt][1]));
                    mB = fmaxf(mB, fmaxf(s[mi][nt][2], s[mi][nt][3]));
                }
                mA = fmaxf(mA, __shfl_xor_sync(0xffffffffu, mA, 1));
                mA = fmaxf(mA, __shfl_xor_sync(0xffffffffu, mA, 2));
                mB = fmaxf(mB, __shfl_xor_sync(0xffffffffu, mB, 1));
                mB = fmaxf(mB, __shfl_xor_sync(0xffffffffu, mB, 2));
                float sA = 0.f, sB = 0.f;
                #pragma unroll
                for (int nt = 0; nt < 8; nt++) {
                    float e0 = __expf(s[mi][nt][0] - mA);
                    float e1 = __expf(s[mi][nt][1] - mA);
                    float e2 = __expf(s[mi][nt][2] - mB);
                    float e3 = __expf(s[mi][nt][3] - mB);
                    s[mi][nt][0]=e0; s[mi][nt][1]=e1; s[mi][nt][2]=e2; s[mi][nt][3]=e3;
                    sA += e0 + e1; sB += e2 + e3;
                }
                sA += __shfl_xor_sync(0xffffffffu, sA, 1);
                sA += __shfl_xor_sync(0xffffffffu, sA, 2);
                sB += __shfl_xor_sync(0xffffffffu, sB, 1);
                sB += __shfl_xor_sync(0xffffffffu, sB, 2);
                invA[mi] = 1.0f / sA;
                invB[mi] = 1.0f / sB;
            }
            float o[2][2][4];
            #pragma unroll
            for (int mi = 0; mi < 2; mi++)
                #pragma unroll
                for (int nt2 = 0; nt2 < 2; nt2++)
                    #pragma unroll
                    for (int e = 0; e < 4; e++) o[mi][nt2][e] = 0.f;
            #pragma unroll
            for (int ks = 0; ks < 4; ks++) {
                unsigned pa[2][4];
                #pragma unroll
                for (int mi = 0; mi < 2; mi++) {
                    pa[mi][0] = pack2(s[mi][2*ks  ][0], s[mi][2*ks  ][1]);
                    pa[mi][1] = pack2(s[mi][2*ks  ][2], s[mi][2*ks  ][3]);
                    pa[mi][2] = pack2(s[mi][2*ks+1][0], s[mi][2*ks+1][1]);
                    pa[mi][3] = pack2(s[mi][2*ks+1][2], s[mi][2*ks+1][3]);
                }
                #pragma unroll
                for (int nt2 = 0; nt2 < 2; nt2++) {
                    const __nv_bfloat16* vp = Vh + (nt2*8 + g)*72 + ks*16;
                    unsigned b0 = *reinterpret_cast<const unsigned*>(vp + 2*tq);
                    unsigned b1 = *reinterpret_cast<const unsigned*>(vp + 2*tq + 8);
                    mma_bf16(o[0][nt2], pa[0], b0, b1);
                    mma_bf16(o[1][nt2], pa[1], b0, b1);
                }
            }
            #pragma unroll
            for (int mi = 0; mi < 2; mi++) {
                const int row = (pass*2+mi)*16 + g;
                #pragma unroll
                for (int nt2 = 0; nt2 < 2; nt2++) {
                    const int dh = nt2*8 + 2*tq;
                    if (dh < 10) {
                        *reinterpret_cast<unsigned*>(sO + row*88 + h*10 + dh) =
                            pack2(o[mi][nt2][0]*invA[mi], o[mi][nt2][1]*invA[mi]);
                        *reinterpret_cast<unsigned*>(sO + (row+8)*88 + h*10 + dh) =
                            pack2(o[mi][nt2][2]*invB[mi], o[mi][nt2][3]*invB[mi]);
                    }
                }
            }
        }
        __syncthreads();

        // ---- proj GEMM (n padded 80->96): 4 mt x 4 groups of 3 ntiles ----
        {
            const int mt = w & 3;
            const int nb = (w >> 2) * 3;
            float acc[3][4];
            #pragma unroll
            for (int j = 0; j < 3; j++)
                #pragma unroll
                for (int e = 0; e < 4; e++) acc[j][e] = 0.f;
            #pragma unroll
            for (int ks = 0; ks < 5; ks++) {
                unsigned a[4];
                const __nv_bfloat16* ap = sO + (mt*16 + g)*88 + ks*16;
                a[0] = *reinterpret_cast<const unsigned*>(ap + 2*tq);
                a[1] = *reinterpret_cast<const unsigned*>(ap + 8*88 + 2*tq);
                a[2] = *reinterpret_cast<const unsigned*>(ap + 2*tq + 8);
                a[3] = *reinterpret_cast<const unsigned*>(ap + 8*88 + 2*tq + 8);
                #pragma unroll
                for (int j = 0; j < 3; j++) {
                    const __nv_bfloat16* bp = sWprojT + ((nb+j)*8 + g)*88 + ks*16;
                    unsigned b0 = *reinterpret_cast<const unsigned*>(bp + 2*tq);
                    unsigned b1 = *reinterpret_cast<const unsigned*>(bp + 2*tq + 8);
                    mma_bf16(acc[j], a, b0, b1);
                }
            }
            const int rowA = mt*16 + g;
            #pragma unroll
            for (int j = 0; j < 3; j++) {
                const int c = (nb+j)*8 + 2*tq;
                if (c < 80) {
                    sXN[rowA*81 + c]         += acc[j][0] + sBproj[c];
                    sXN[rowA*81 + c + 1]     += acc[j][1] + sBproj[c+1];
                    sXN[(rowA+8)*81 + c]     += acc[j][2] + sBproj[c];
                    sXN[(rowA+8)*81 + c + 1] += acc[j][3] + sBproj[c+1];
                }
            }
        }
        __syncthreads();

        // ---- coalesced store (8 thr/token, float2) ----
        {
            const int t = tid >> 3, lg = tid & 7;
            const int ti = t >> 3, tj = t & 7;
            int pr, pc;
            if (IS_GRID) { pr = ti*16 + wh; pc = tj*16 + ww; }
            else         { pr = wh*8 + ti;  pc = ww*8 + tj;  }
            const long pix = ((long)bb*128 + pr)*128 + pc;
            float2* yr = reinterpret_cast<float2*>(y + pix*80) + lg*5;
            const float* xn = sXN + t*81 + lg*10;
            #pragma unroll
            for (int u = 0; u < 5; u++)
                yr[u] = make_float2(xn[2*u], xn[2*u+1]);
        }
        __syncthreads();   // before next tile overwrites smem
    }
}

// =====================================================================
// Fused MLP via bf16 mma, 512 threads = 16 warps.
// GEMM1: 4 mt x 4 n-groups (10 ntiles).  GEMM2: 4 mt x 2 n-groups x 2 k-halves,
// partial sums in two fp32 buffers aliasing sH, combined in epilogue.
//
// smem layout (bytes):
//   sW1T [320][88] bf16 @      0  (56320)
//   sW2T [ 80][344] bf16 @ 56320  (55040)
//   sXN  [64][81] f32   @ 111360  (20736)
//   sXNh [64][88] bf16  @ 132096  (11264)
//   sH   [64][344] bf16 @ 143360  (44032)  (aliased by sOutA/sOutB f32 [64][81] x2)
//   sB2  [80] f32       @ 187392
//   sG   [80] f32       @ 187712
// total 188032 B
// =====================================================================
constexpr int MLP_SMEM_BYTES = 188032;
constexpr int MLP_TILES_PER_CTA = 4;
constexpr int MLP_NCTA = (TOK_TOTAL/64) / MLP_TILES_PER_CTA;  // 2048

template<bool RELU2>
__global__ void __launch_bounds__(512, 1)
mlp_kernel(const float* __restrict__ xin, float* __restrict__ xout,
           const float* __restrict__ w1, const float* __restrict__ w2,
           const float* __restrict__ b2, const float* __restrict__ gamma)
{
    extern __shared__ float smf[];
    char* smb = reinterpret_cast<char*>(smf);
    __nv_bfloat16* sW1T  = reinterpret_cast<__nv_bfloat16*>(smb);            // [320][88]
    __nv_bfloat16* sW2T  = reinterpret_cast<__nv_bfloat16*>(smb + 56320);    // [80][344]
    float*         sXN   = reinterpret_cast<float*>(smb + 111360);           // [64][81]
    __nv_bfloat16* sXNh  = reinterpret_cast<__nv_bfloat16*>(smb + 132096);   // [64][88]
    __nv_bfloat16* sH    = reinterpret_cast<__nv_bfloat16*>(smb + 143360);   // [64][344]
    float*         sOutA = reinterpret_cast<float*>(smb + 143360);           // alias
    float*         sOutB = reinterpret_cast<float*>(smb + 164096);           // alias
    float*         sB2   = reinterpret_cast<float*>(smb + 187392);
    float*         sG    = reinterpret_cast<float*>(smb + 187712);

    const int tid = threadIdx.x;

    for (int idx = tid; idx < 25600; idx += 512) {
        { int k = idx / 320, n = idx % 320; sW1T[n*88  + k] = __float2bfloat16(w1[idx]); }
        { int k = idx / 80,  n = idx % 80;  sW2T[n*344 + k] = __float2bfloat16(w2[idx]); }
    }
    if (tid < 80) { sB2[tid] = b2[tid]; sG[tid] = gamma[tid]; }

    const int w    = tid >> 5, lane = tid & 31;
    const int g    = lane >> 2, tq  = lane & 3;

    for (int it = 0; it < MLP_TILES_PER_CTA; it++) {
        const long tokBase = ((long)blockIdx.x * MLP_TILES_PER_CTA + it) * 64;

        // ---- load + l2norm (8 thr/token, float2) ----
        {
            const int t = tid >> 3, lg = tid & 7;
            const float2* xr = reinterpret_cast<const float2*>(xin + (tokBase + t)*80) + lg*5;
            float v[10]; float ssq = 0.f;
            #pragma unroll
            for (int u = 0; u < 5; u++) {
                float2 f = xr[u];
                v[2*u]=f.x; v[2*u+1]=f.y;
                ssq += f.x*f.x + f.y*f.y;
            }
            ssq += __shfl_xor_sync(0xffffffffu, ssq, 1);
            ssq += __shfl_xor_sync(0xffffffffu, ssq, 2);
            ssq += __shfl_xor_sync(0xffffffffu, ssq, 4);
            const float inv = rsqrtf(fmaxf(ssq, 1e-24f));
            float* xn = sXN + t*81 + lg*10;
            unsigned* xh = reinterpret_cast<unsigned*>(sXNh + t*88 + lg*10);
            #pragma unroll
            for (int u = 0; u < 10; u++) { v[u] *= inv; xn[u] = v[u]; }
            #pragma unroll
            for (int u = 0; u < 5; u++) xh[u] = pack2(v[2*u], v[2*u+1]);
        }
        __syncthreads();

        // ---- GEMM1: 16 warps = 4 mt x 4 n-groups of 10 ntiles ----
        {
            const int mt    = w & 3;
            const int nbase = (w >> 2) * 10;
            float acc[10][4];
            #pragma unroll
            for (int j = 0; j < 10; j++)
                #pragma unroll
                for (int e = 0; e < 4; e++) acc[j][e] = 0.f;

            #pragma unroll
            for (int ks = 0; ks < 5; ks++) {
                unsigned a[4];
                const __nv_bfloat16* ap = sXNh + (mt*16 + g)*88 + ks*16;
                a[0] = *reinterpret_cast<const unsigned*>(ap + 2*tq);
                a[1] = *reinterpret_cast<const unsigned*>(ap + 8*88 + 2*tq);
                a[2] = *reinterpret_cast<const unsigned*>(ap + 8 + 2*tq);
                a[3] = *reinterpret_cast<const unsigned*>(ap + 8*88 + 8 + 2*tq);
                #pragma unroll
                for (int j = 0; j < 10; j++) {
                    const __nv_bfloat16* bp = sW1T + ((nbase+j)*8 + g)*88 + ks*16;
                    unsigned b0 = *reinterpret_cast<const unsigned*>(bp + 2*tq);
                    unsigned b1 = *reinterpret_cast<const unsigned*>(bp + 8 + 2*tq);
                    mma_bf16(acc[j], a, b0, b1);
                }
            }
            const int r0 = mt*16 + g;
            #pragma unroll
            for (int j = 0; j < 10; j++) {
                const int c = (nbase+j)*8 + 2*tq;
                *reinterpret_cast<unsigned*>(sH + r0*344 + c) =
                    pack2(fmaxf(acc[j][0], 0.f), fmaxf(acc[j][1], 0.f));
                *reinterpret_cast<unsigned*>(sH + (r0+8)*344 + c) =
                    pack2(fmaxf(acc[j][2], 0.f), fmaxf(acc[j][3], 0.f));
            }
        }
        __syncthreads();

        // ---- GEMM2: 4 mt x 2 n-groups x 2 k-halves ----
        {
            const int mt = w & 3;
            const int nb = ((w >> 2) & 1) * 5;
            const int kh = w >> 3;
            float acc2[5][4];
            #pragma unroll
            for (int j = 0; j < 5; j++)
                #pragma unroll
                for (int e = 0; e < 4; e++) acc2[j][e] = 0.f;

            #pragma unroll
            for (int ks = 0; ks < 10; ks++) {
                const int kk = kh*10 + ks;
                unsigned a[4];
                const __nv_bfloat16* ap = sH + (mt*16 + g)*344 + kk*16;
                a[0] = *reinterpret_cast<const unsigned*>(ap + 2*tq);
                a[1] = *reinterpret_cast<const unsigned*>(ap + 8*344 + 2*tq);
                a[2] = *reinterpret_cast<const unsigned*>(ap + 8 + 2*tq);
                a[3] = *reinterpret_cast<const unsigned*>(ap + 8*344 + 8 + 2*tq);
                #pragma unroll
                for (int j = 0; j < 5; j++) {
                    const __nv_bfloat16* bp = sW2T + ((nb+j)*8 + g)*344 + kk*16;
                    unsigned b0 = *reinterpret_cast<const unsigned*>(bp + 2*tq);
                    unsigned b1 = *reinterpret_cast<const unsigned*>(bp + 8 + 2*tq);
                    mma_bf16(acc2[j], a, b0, b1);
                }
            }
            __syncthreads();   // all warps done reading sH before overwrite
            float* sOut = kh ? sOutB : sOutA;
            const int r0 = mt*16 + g;
            #pragma unroll
            for (int j = 0; j < 5; j++) {
                const int c = (nb+j)*8 + 2*tq;
                sOut[r0*81 + c]         = acc2[j][0];
                sOut[r0*81 + c + 1]     = acc2[j][1];
                sOut[(r0+8)*81 + c]     = acc2[j][2];
                sOut[(r0+8)*81 + c + 1] = acc2[j][3];
            }
        }
        __syncthreads();

        // ---- epilogue: out = XN + act(A+B+b2)*gamma (8 thr/token) ----
        {
            const int t = tid >> 3, lg = tid & 7;
            float2* yr = reinterpret_cast<float2*>(xout + (tokBase + t)*80) + lg*5;
            #pragma unroll
            for (int u = 0; u < 5; u++) {
                float f[2];
                #pragma unroll
                for (int e = 0; e < 2; e++) {
                    const int idx = lg*10 + 2*u + e;
                    float hv = sOutA[t*81 + idx] + sOutB[t*81 + idx] + sB2[idx];
                    if (RELU2) hv = fmaxf(hv, 0.f);
                    f[e] = sXN[t*81 + idx] + hv * sG[idx];
                }
                yr[u] = make_float2(f[0], f[1]);
            }
        }
        __syncthreads();
    }
}

// =====================================================================
extern "C" void kernel_launch(void* const* d_in, const int* in_sizes, int n_in,
                              void* d_out, int out_size)
{
    const float* x       = (const float*)d_in[0];
    const float* bw_qkv  = (const float*)d_in[1];
    const float* bb_qkv  = (const float*)d_in[2];
    const float* bw_proj = (const float*)d_in[3];
    const float* bb_proj = (const float*)d_in[4];
    const float* b_gamma = (const float*)d_in[5];
    const float* bw_mlp1 = (const float*)d_in[6];
    const float* bw_mlp2 = (const float*)d_in[7];
    const float* bb_mlp2 = (const float*)d_in[8];
    const float* gw_qkv  = (const float*)d_in[9];
    const float* gb_qkv  = (const float*)d_in[10];
    const float* gw_proj = (const float*)d_in[11];
    const float* gb_proj = (const float*)d_in[12];
    const float* g_gamma = (const float*)d_in[13];
    const float* gw_mlp1 = (const float*)d_in[14];
    const float* gw_mlp2 = (const float*)d_in[15];
    const float* gb_mlp2 = (const float*)d_in[16];
    float* out = (float*)d_out;

    float *buf1 = nullptr, *buf2 = nullptr;
    cudaGetSymbolAddress((void**)&buf1, g_buf1);
    cudaGetSymbolAddress((void**)&buf2, g_buf2);

    const size_t smA = ATTN_SMEM_BYTES;   // 161,792 B
    const size_t smM = MLP_SMEM_BYTES;    // 188,032 B
    cudaFuncSetAttribute(attn_kernel<false>, cudaFuncAttributeMaxDynamicSharedMemorySize, (int)smA);
    cudaFuncSetAttribute(attn_kernel<true>,  cudaFuncAttributeMaxDynamicSharedMemorySize, (int)smA);
    cudaFuncSetAttribute(mlp_kernel<true>,   cudaFuncAttributeMaxDynamicSharedMemorySize, (int)smM);
    cudaFuncSetAttribute(mlp_kernel<false>,  cudaFuncAttributeMaxDynamicSharedMemorySize, (int)smM);

    // stage 1: block SA
    attn_kernel<false><<<ATTN_NCTA, 512, smA>>>(x,    buf1, bw_qkv, bb_qkv, bw_proj, bb_proj);
    mlp_kernel<true>  <<<MLP_NCTA,  512, smM>>>(buf1, buf2, bw_mlp1, bw_mlp2, bb_mlp2, b_gamma);
    // stage 2: grid SA
    attn_kernel<true> <<<ATTN_NCTA, 512, smA>>>(buf2, buf1, gw_qkv, gb_qkv, gw_proj, gb_proj);
    mlp_kernel<false> <<<MLP_NCTA,  512, smM>>>(buf1, out, gw_mlp1, gw_mlp2, gb_mlp2, g_gamma);
}

// round 7
// speedup vs baseline: 1.2743x; 1.2743x over previous
#include <cuda_runtime.h>
#include <cuda_bf16.h>

// ---------------- problem constants ----------------
// x: (32, 128, 128, 80) fp32; C=80, NH=8, DH=10, WIN=GRID=8 -> 64-token windows
// windows per stage: 32 * 16 * 16 = 8192 ; tokens total 524288

#define TOK_TOTAL (32*128*128)

__device__ float g_buf1[(size_t)TOK_TOTAL * 80];
__device__ float g_buf2[(size_t)TOK_TOTAL * 80];

// pre-converted transposed bf16 weight panels (written by prep_kernel)
__device__ __align__(16) __nv_bfloat16 g_qkvT_b[240*88];
__device__ __align__(16) __nv_bfloat16 g_projT_b[80*88];
__device__ __align__(16) __nv_bfloat16 g_qkvT_g[240*88];
__device__ __align__(16) __nv_bfloat16 g_projT_g[80*88];
__device__ __align__(16) __nv_bfloat16 g_w1T_b[320*88];
__device__ __align__(16) __nv_bfloat16 g_w2T_b[80*344];
__device__ __align__(16) __nv_bfloat16 g_w1T_g[320*88];
__device__ __align__(16) __nv_bfloat16 g_w2T_g[80*344];

// ---------------- helpers ----------------
__device__ __forceinline__ unsigned pack2(float lo, float hi) {
    __nv_bfloat162 t = __floats2bfloat162_rn(lo, hi);
    return *reinterpret_cast<unsigned*>(&t);
}

__device__ __forceinline__ void mma_bf16(float* c, const unsigned* a, unsigned b0, unsigned b1) {
    asm volatile(
        "mma.sync.aligned.m16n8k16.row.col.f32.bf16.bf16.f32 "
        "{%0,%1,%2,%3}, {%4,%5,%6,%7}, {%8,%9}, {%0,%1,%2,%3};\n"
        : "+f"(c[0]), "+f"(c[1]), "+f"(c[2]), "+f"(c[3])
        : "r"(a[0]), "r"(a[1]), "r"(a[2]), "r"(a[3]), "r"(b0), "r"(b1));
}

__device__ __forceinline__ unsigned smem_u32(const void* p) {
    return (unsigned)__cvta_generic_to_shared(p);
}

__device__ __forceinline__ void ldsm_x4(unsigned* r, unsigned addr) {
    asm volatile("ldmatrix.sync.aligned.m8n8.x4.shared.b16 {%0,%1,%2,%3}, [%4];\n"
                 : "=r"(r[0]), "=r"(r[1]), "=r"(r[2]), "=r"(r[3]) : "r"(addr));
}
__device__ __forceinline__ void ldsm_x2(unsigned& r0, unsigned& r1, unsigned addr) {
    asm volatile("ldmatrix.sync.aligned.m8n8.x2.shared.b16 {%0,%1}, [%2];\n"
                 : "=r"(r0), "=r"(r1) : "r"(addr));
}

// ---------------- prepass: W[k][n] f32 -> WT[n][stride] bf16 (pads zero) ----
__global__ void prep_kernel(const float* __restrict__ src, __nv_bfloat16* __restrict__ dst,
                            int K, int N, int stride, int rowsTot)
{
    const int total = rowsTot * stride;
    for (int idx = blockIdx.x*256 + threadIdx.x; idx < total; idx += gridDim.x*256) {
        int n = idx / stride, k = idx - n*stride;
        float v = (n < N && k < K) ? src[k*N + n] : 0.f;
        dst[idx] = __float2bfloat16(v);
    }
}

// =====================================================================
// Fused window attention (R4 structure) + ldmatrix + prestaged weights.
// 256 threads = 8 warps; 4 windows per CTA.
// smem layout identical to R4 (156160 B).
// =====================================================================
constexpr int ATTN_SMEM_BYTES = 156160;
constexpr int ATTN_TILES_PER_CTA = 4;
constexpr int ATTN_NCTA = 8192 / ATTN_TILES_PER_CTA;   // 2048
constexpr float QK_SCALE = 0.31622776601683794f;       // DH^-0.5

template<bool IS_GRID>
__global__ void __launch_bounds__(256, 1)
attn_kernel(const float* __restrict__ x, float* __restrict__ y,
            const __nv_bfloat16* __restrict__ wqkvT, const float* __restrict__ bqkv,
            const __nv_bfloat16* __restrict__ wprojT, const float* __restrict__ bproj)
{
    extern __shared__ float smf[];
    char* smb = reinterpret_cast<char*>(smf);
    __nv_bfloat16* sWqkvT  = reinterpret_cast<__nv_bfloat16*>(smb);           // [240][88]
    __nv_bfloat16* sWprojT = reinterpret_cast<__nv_bfloat16*>(smb + 42240);   // [80][88]
    float*         sXN     = reinterpret_cast<float*>(smb + 56320);           // [64][81]
    __nv_bfloat16* sXNh    = reinterpret_cast<__nv_bfloat16*>(smb + 77056);   // [64][88]
    __nv_bfloat16* sQ      = reinterpret_cast<__nv_bfloat16*>(smb + 88320);   // [8][64][18]
    __nv_bfloat16* sK      = reinterpret_cast<__nv_bfloat16*>(smb + 106752);  // [8][64][18]
    __nv_bfloat16* sVT     = reinterpret_cast<__nv_bfloat16*>(smb + 125184);  // [8][16][72]
    __nv_bfloat16* sO      = reinterpret_cast<__nv_bfloat16*>(smb + 143616);  // [64][88]
    float*         sBqkv   = reinterpret_cast<float*>(smb + 154880);          // [240]
    float*         sBproj  = reinterpret_cast<float*>(smb + 155840);          // [80]

    const int tid  = threadIdx.x;
    const int w    = tid >> 5, lane = tid & 31;
    const int g    = lane >> 2, tq  = lane & 3;
    const int l15  = lane & 15, l7 = lane & 7;

    // ---- one-time staging: vector copies of pre-converted weights ----
    {
        const float4* s1 = reinterpret_cast<const float4*>(wqkvT);
        float4* d1 = reinterpret_cast<float4*>(sWqkvT);
        for (int i = tid; i < 2640; i += 256) d1[i] = s1[i];     // 42240/16
        const float4* s2 = reinterpret_cast<const float4*>(wprojT);
        float4* d2 = reinterpret_cast<float4*>(sWprojT);
        for (int i = tid; i < 880; i += 256) d2[i] = s2[i];      // 14080/16
        if (tid < 240) sBqkv[tid] = bqkv[tid];
        if (tid < 80)  sBproj[tid] = bproj[tid];
    }
    // zero k-pads d=10..17 of sQ and sK (stay zero across tiles)
    for (int i = tid; i < 2048; i += 256) {
        int row = i >> 2, p = i & 3;
        reinterpret_cast<unsigned*>(sQ + row*18 + 10)[p] = 0u;
        reinterpret_cast<unsigned*>(sK + row*18 + 10)[p] = 0u;
    }

    const unsigned uXNh = smem_u32(sXNh);
    const unsigned uWq  = smem_u32(sWqkvT);
    const unsigned uO   = smem_u32(sO);
    const unsigned uWp  = smem_u32(sWprojT);

    for (int it = 0; it < ATTN_TILES_PER_CTA; it++) {
        const int wIdx = blockIdx.x * ATTN_TILES_PER_CTA + it;
        const int bb  = wIdx >> 8;
        const int rem = wIdx & 255;
        const int wh  = rem >> 4, ww = rem & 15;

        // ---- load + l2norm (4 threads per token, float4) ----
        {
            const int t = tid >> 2, lg = tid & 3;
            const int ti = t >> 3, tj = t & 7;
            int pr, pc;
            if (IS_GRID) { pr = ti*16 + wh; pc = tj*16 + ww; }
            else         { pr = wh*8 + ti;  pc = ww*8 + tj;  }
            const long pix = ((long)bb*128 + pr)*128 + pc;
            const float4* xr = reinterpret_cast<const float4*>(x + pix*80) + lg*5;
            float v[20]; float ss = 0.f;
            #pragma unroll
            for (int u = 0; u < 5; u++) {
                float4 f = xr[u];
                v[4*u+0]=f.x; v[4*u+1]=f.y; v[4*u+2]=f.z; v[4*u+3]=f.w;
                ss += f.x*f.x + f.y*f.y + f.z*f.z + f.w*f.w;
            }
            ss += __shfl_xor_sync(0xffffffffu, ss, 1);
            ss += __shfl_xor_sync(0xffffffffu, ss, 2);
            const float inv = rsqrtf(fmaxf(ss, 1e-24f));
            float* xn = sXN + t*81 + lg*20;
            unsigned* xh = reinterpret_cast<unsigned*>(sXNh + t*88 + lg*20);
            #pragma unroll
            for (int u = 0; u < 20; u++) { v[u] *= inv; xn[u] = v[u]; }
            #pragma unroll
            for (int u = 0; u < 10; u++) xh[u] = pack2(v[2*u], v[2*u+1]);
        }
        __syncthreads();

        // ---- QKV GEMM: 8 warps = 4 mt x 2 j-groups of 15 ntiles (ldmatrix) ----
        {
            const int mt    = w >> 1;
            const int jbase = (w & 1) * 15;
            const unsigned aBase = uXNh + (mt*16 + l15)*176 + (lane>>4)*16;
            const unsigned bBase = uWq + (jbase*8 + l7)*176 + (l15>>3)*16;
            float acc[15][4];
            #pragma unroll
            for (int j = 0; j < 15; j++)
                #pragma unroll
                for (int e = 0; e < 4; e++) acc[j][e] = 0.f;

            #pragma unroll
            for (int ks = 0; ks < 5; ks++) {
                unsigned a[4];
                ldsm_x4(a, aBase + ks*32);
                #pragma unroll
                for (int j = 0; j < 15; j++) {
                    unsigned b0, b1;
                    ldsm_x2(b0, b1, bBase + j*1408 + ks*32);   // 8*176 = 1408
                    mma_bf16(acc[j], a, b0, b1);
                }
            }
            const int rowA = mt*16 + g;
            #pragma unroll
            for (int j = 0; j < 15; j++) {
                #pragma unroll
                for (int e = 0; e < 2; e++) {
                    const int col = (jbase+j)*8 + 2*tq + e;
                    const int h = col / 30;
                    const int r = col - h*30;
                    const int d = (r >= 20) ? r - 20 : (r >= 10 ? r - 10 : r);
                    const float bias = sBqkv[col];
                    float vA = acc[j][e]   + bias;
                    float vB = acc[j][2+e] + bias;
                    if (r < 10) {
                        sQ[h*1152 + rowA*18 + d]     = __float2bfloat16(vA * QK_SCALE);
                        sQ[h*1152 + (rowA+8)*18 + d] = __float2bfloat16(vB * QK_SCALE);
                    } else if (r < 20) {
                        sK[h*1152 + rowA*18 + d]     = __float2bfloat16(vA);
                        sK[h*1152 + (rowA+8)*18 + d] = __float2bfloat16(vB);
                    } else {
                        sVT[h*1152 + d*72 + rowA]     = __float2bfloat16(vA);
                        sVT[h*1152 + d*72 + rowA + 8] = __float2bfloat16(vB);
                    }
                }
            }
        }
        __syncthreads();

        // ---- attention: warp w == head w, register-resident (2 passes) ----
        {
            const int h = w;
            const __nv_bfloat16* Qh = sQ  + h*1152;
            const __nv_bfloat16* Kh = sK  + h*1152;
            const __nv_bfloat16* Vh = sVT + h*1152;

            #pragma unroll
            for (int pass = 0; pass < 2; pass++) {
                float s[2][8][4];
                unsigned qa[2][4];
                #pragma unroll
                for (int mi = 0; mi < 2; mi++) {
                    const __nv_bfloat16* qp = Qh + ((pass*2+mi)*16 + g)*18;
                    qa[mi][0] = *reinterpret_cast<const unsigned*>(qp + 2*tq);
                    qa[mi][1] = *reinterpret_cast<const unsigned*>(qp + 8*18 + 2*tq);
                    qa[mi][2] = *reinterpret_cast<const unsigned*>(qp + 2*tq + 8);
                    qa[mi][3] = *reinterpret_cast<const unsigned*>(qp + 8*18 + 2*tq + 8);
                }
                #pragma unroll
                for (int nt = 0; nt < 8; nt++) {
                    const __nv_bfloat16* kp = Kh + (nt*8 + g)*18;
                    unsigned b0 = *reinterpret_cast<const unsigned*>(kp + 2*tq);
                    unsigned b1 = *reinterpret_cast<const unsigned*>(kp + 2*tq + 8);
                    #pragma unroll
                    for (int mi = 0; mi < 2; mi++) {
                        #pragma unroll
                        for (int e = 0; e < 4; e++) s[mi][nt][e] = 0.f;
                        mma_bf16(s[mi][nt], qa[mi], b0, b1);
                    }
                }
                float invA[2], invB[2];
                #pragma unroll
                for (int mi = 0; mi < 2; mi++) {
                    float mA = -1e30f, mB = -1e30f;
                    #pragma unroll
                    for (int nt = 0; nt < 8; nt++) {
                        mA = fmaxf(mA, fmaxf(s[mi][nt][0], s[mi][nt][1]));
                        mB = fmaxf(mB, fmaxf(s[mi][nt][2], s[mi][nt][3]));
                    }
                    mA = fmaxf(mA, __shfl_xor_sync(0xffffffffu, mA, 1));
                    mA = fmaxf(mA, __shfl_xor_sync(0xffffffffu, mA, 2));
                    mB = fmaxf(mB, __shfl_xor_sync(0xffffffffu, mB, 1));
                    mB = fmaxf(mB, __shfl_xor_sync(0xffffffffu, mB, 2));
                    float sA = 0.f, sB = 0.f;
                    #pragma unroll
                    for (int nt = 0; nt < 8; nt++) {
                        float e0 = __expf(s[mi][nt][0] - mA);
                        float e1 = __expf(s[mi][nt][1] - mA);
                        float e2 = __expf(s[mi][nt][2] - mB);
                        float e3 = __expf(s[mi][nt][3] - mB);
                        s[mi][nt][0]=e0; s[mi][nt][1]=e1; s[mi][nt][2]=e2; s[mi][nt][3]=e3;
                        sA += e0 + e1; sB += e2 + e3;
                    }
                    sA += __shfl_xor_sync(0xffffffffu, sA, 1);
                    sA += __shfl_xor_sync(0xffffffffu, sA, 2);
                    sB += __shfl_xor_sync(0xffffffffu, sB, 1);
                    sB += __shfl_xor_sync(0xffffffffu, sB, 2);
                    invA[mi] = 1.0f / sA;
                    invB[mi] = 1.0f / sB;
                }
                float o[2][2][4];
                #pragma unroll
                for (int mi = 0; mi < 2; mi++)
                    #pragma unroll
                    for (int nt2 = 0; nt2 < 2; nt2++)
                        #pragma unroll
                        for (int e = 0; e < 4; e++) o[mi][nt2][e] = 0.f;
                #pragma unroll
                for (int ks = 0; ks < 4; ks++) {
                    unsigned pa[2][4];
                    #pragma unroll
                    for (int mi = 0; mi < 2; mi++) {
                        pa[mi][0] = pack2(s[mi][2*ks  ][0], s[mi][2*ks  ][1]);
                        pa[mi][1] = pack2(s[mi][2*ks  ][2], s[mi][2*ks  ][3]);
                        pa[mi][2] = pack2(s[mi][2*ks+1][0], s[mi][2*ks+1][1]);
                        pa[mi][3] = pack2(s[mi][2*ks+1][2], s[mi][2*ks+1][3]);
                    }
                    #pragma unroll
                    for (int nt2 = 0; nt2 < 2; nt2++) {
                        const __nv_bfloat16* vp = Vh + (nt2*8 + g)*72 + ks*16;
                        unsigned b0 = *reinterpret_cast<const unsigned*>(vp + 2*tq);
                        unsigned b1 = *reinterpret_cast<const unsigned*>(vp + 2*tq + 8);
                        mma_bf16(o[0][nt2], pa[0], b0, b1);
                        mma_bf16(o[1][nt2], pa[1], b0, b1);
                    }
                }
                #pragma unroll
                for (int mi = 0; mi < 2; mi++) {
                    const int row = (pass*2+mi)*16 + g;
                    #pragma unroll
                    for (int nt2 = 0; nt2 < 2; nt2++) {
                        const int dh = nt2*8 + 2*tq;
                        if (dh < 10) {
                            *reinterpret_cast<unsigned*>(sO + row*88 + h*10 + dh) =
                                pack2(o[mi][nt2][0]*invA[mi], o[mi][nt2][1]*invA[mi]);
                            *reinterpret_cast<unsigned*>(sO + (row+8)*88 + h*10 + dh) =
                                pack2(o[mi][nt2][2]*invB[mi], o[mi][nt2][3]*invB[mi]);
                        }
                    }
                }
            }
        }
        __syncthreads();

        // ---- proj GEMM: 4 mt x 2 groups of 5 ntiles (ldmatrix) ----
        {
            const int mt = w >> 1;
            const int nb = (w & 1) * 5;
            const unsigned aBase = uO + (mt*16 + l15)*176 + (lane>>4)*16;
            const unsigned bBase = uWp + (nb*8 + l7)*176 + (l15>>3)*16;
            float acc[5][4];
            #pragma unroll
            for (int j = 0; j < 5; j++)
                #pragma unroll
                for (int e = 0; e < 4; e++) acc[j][e] = 0.f;
            #pragma unroll
            for (int ks = 0; ks < 5; ks++) {
                unsigned a[4];
                ldsm_x4(a, aBase + ks*32);
                #pragma unroll
                for (int j = 0; j < 5; j++) {
                    unsigned b0, b1;
                    ldsm_x2(b0, b1, bBase + j*1408 + ks*32);
                    mma_bf16(acc[j], a, b0, b1);
                }
            }
            const int rowA = mt*16 + g;
            #pragma unroll
            for (int j = 0; j < 5; j++) {
                const int c = (nb+j)*8 + 2*tq;
                sXN[rowA*81 + c]         += acc[j][0] + sBproj[c];
                sXN[rowA*81 + c + 1]     += acc[j][1] + sBproj[c+1];
                sXN[(rowA+8)*81 + c]     += acc[j][2] + sBproj[c];
                sXN[(rowA+8)*81 + c + 1] += acc[j][3] + sBproj[c+1];
            }
        }
        __syncthreads();

        // ---- coalesced store ----
        {
            const int t = tid >> 2, lg = tid & 3;
            const int ti = t >> 3, tj = t & 7;
            int pr, pc;
            if (IS_GRID) { pr = ti*16 + wh; pc = tj*16 + ww; }
            else         { pr = wh*8 + ti;  pc = ww*8 + tj;  }
            const long pix = ((long)bb*128 + pr)*128 + pc;
            float4* yr = reinterpret_cast<float4*>(y + pix*80) + lg*5;
            const float* xn = sXN + t*81 + lg*20;
            #pragma unroll
            for (int u = 0; u < 5; u++)
                yr[u] = make_float4(xn[4*u], xn[4*u+1], xn[4*u+2], xn[4*u+3]);
        }
        __syncthreads();
    }
}

// =====================================================================
// Fused MLP, M=128 supertiles, 512 threads = 16 warps, ldmatrix.
// Per CTA: 2 supertiles (grid 2048).  Residual recomputed in epilogue
// (reload x, scale by sInv) -> no fp32 XN buffer.
//
// smem (bytes):
//   sW1T [320][88] bf16 @      0  (56320)
//   sW2T [ 80][344] bf16 @ 56320  (55040)
//   sXNh [128][88] bf16 @ 111360  (22528)
//   sH   [128][344] bf16 @ 133888 (88064)  aliased by sOutA/sOutB f32 [128][81]
//   sInv [128] f32      @ 221952  (512)
//   sB2  [80] f32       @ 222464
//   sG   [80] f32       @ 222784
// total 223104 B
// =====================================================================
constexpr int MLP_SMEM_BYTES = 223104;
constexpr int MLP_NCTA = TOK_TOTAL / 256;   // 2048, 2 supertiles of 128 each

template<bool RELU2>
__global__ void __launch_bounds__(512, 1)
mlp_kernel(const float* __restrict__ xin, float* __restrict__ xout,
           const __nv_bfloat16* __restrict__ w1T, const __nv_bfloat16* __restrict__ w2T,
           const float* __restrict__ b2, const float* __restrict__ gamma)
{
    extern __shared__ float smf[];
    char* smb = reinterpret_cast<char*>(smf);
    __nv_bfloat16* sW1T  = reinterpret_cast<__nv_bfloat16*>(smb);            // [320][88]
    __nv_bfloat16* sW2T  = reinterpret_cast<__nv_bfloat16*>(smb + 56320);    // [80][344]
    __nv_bfloat16* sXNh  = reinterpret_cast<__nv_bfloat16*>(smb + 111360);   // [128][88]
    __nv_bfloat16* sH    = reinterpret_cast<__nv_bfloat16*>(smb + 133888);   // [128][344]
    float*         sOutA = reinterpret_cast<float*>(smb + 133888);           // alias [128][81]
    float*         sOutB = reinterpret_cast<float*>(smb + 175360);           // alias [128][81]
    float*         sInv  = reinterpret_cast<float*>(smb + 221952);           // [128]
    float*         sB2   = reinterpret_cast<float*>(smb + 222464);
    float*         sG    = reinterpret_cast<float*>(smb + 222784);

    const int tid = threadIdx.x;
    const int w = tid >> 5, lane = tid & 31;
    const int g = lane >> 2, tq = lane & 3;
    const int l15 = lane & 15, l7 = lane & 7;

    // ---- staging: vector copies of pre-converted weights ----
    {
        const float4* s1 = reinterpret_cast<const float4*>(w1T);
        float4* d1 = reinterpret_cast<float4*>(sW1T);
        for (int i = tid; i < 3520; i += 512) d1[i] = s1[i];     // 56320/16
        const float4* s2 = reinterpret_cast<const float4*>(w2T);
        float4* d2 = reinterpret_cast<float4*>(sW2T);
        for (int i = tid; i < 3440; i += 512) d2[i] = s2[i];     // 55040/16
        if (tid < 80) { sB2[tid] = b2[tid]; sG[tid] = gamma[tid]; }
    }

    const unsigned uXNh = smem_u32(sXNh);
    const unsigned uW1  = smem_u32(sW1T);
    const unsigned uH   = smem_u32(sH);
    const unsigned uW2  = smem_u32(sW2T);

    for (int st = 0; st < 2; st++) {
        const long tokBase = ((long)blockIdx.x*2 + st) * 128;

        // ---- load + l2norm (4 thr/token, float4); keep only inv + bf16 panel ----
        {
            const int t = tid >> 2, lg = tid & 3;
            const float4* xr = reinterpret_cast<const float4*>(xin + (tokBase + t)*80) + lg*5;
            float v[20]; float ss = 0.f;
            #pragma unroll
            for (int u = 0; u < 5; u++) {
                float4 f = xr[u];
                v[4*u]=f.x; v[4*u+1]=f.y; v[4*u+2]=f.z; v[4*u+3]=f.w;
                ss += f.x*f.x + f.y*f.y + f.z*f.z + f.w*f.w;
            }
            ss += __shfl_xor_sync(0xffffffffu, ss, 1);
            ss += __shfl_xor_sync(0xffffffffu, ss, 2);
            const float inv = rsqrtf(fmaxf(ss, 1e-24f));
            unsigned* xh = reinterpret_cast<unsigned*>(sXNh + t*88 + lg*20);
            #pragma unroll
            for (int u = 0; u < 10; u++) xh[u] = pack2(v[2*u]*inv, v[2*u+1]*inv);
            if (lg == 0) sInv[t] = inv;
        }
        __syncthreads();

        // ---- GEMM1: H[128,320] = relu(XNh @ W1); 16 warps = 4 mp x 4 ng ----
        {
            const int mp = w & 3;          // m-pair -> rows mp*32..mp*32+31
            const int ng = w >> 2;         // n-tiles ng*10..ng*10+9
            const unsigned aBase = uXNh + (mp*32 + l15)*176 + (lane>>4)*16;
            const unsigned bBase = uW1 + (ng*80 + l7)*176 + (l15>>3)*16;
            float acc[2][10][4];
            #pragma unroll
            for (int mi = 0; mi < 2; mi++)
                #pragma unroll
                for (int j = 0; j < 10; j++)
                    #pragma unroll
                    for (int e = 0; e < 4; e++) acc[mi][j][e] = 0.f;

            #pragma unroll
            for (int ks = 0; ks < 5; ks++) {
                unsigned a[2][4];
                ldsm_x4(a[0], aBase + ks*32);
                ldsm_x4(a[1], aBase + 16*176 + ks*32);
                #pragma unroll
                for (int j = 0; j < 10; j++) {
                    unsigned b0, b1;
                    ldsm_x2(b0, b1, bBase + j*1408 + ks*32);
                    mma_bf16(acc[0][j], a[0], b0, b1);
                    mma_bf16(acc[1][j], a[1], b0, b1);
                }
            }
            #pragma unroll
            for (int mi = 0; mi < 2; mi++) {
                const int r0 = mp*32 + mi*16 + g;
                #pragma unroll
                for (int j = 0; j < 10; j++) {
                    const int c = (ng*10+j)*8 + 2*tq;
                    *reinterpret_cast<unsigned*>(sH + r0*344 + c) =
                        pack2(fmaxf(acc[mi][j][0], 0.f), fmaxf(acc[mi][j][1], 0.f));
                    *reinterpret_cast<unsigned*>(sH + (r0+8)*344 + c) =
                        pack2(fmaxf(acc[mi][j][2], 0.f), fmaxf(acc[mi][j][3], 0.f));
                }
            }
        }
        __syncthreads();

        // ---- GEMM2: D[128,80] = H @ W2; 16 warps = 4 mp x 2 ng x 2 kh ----
        {
            const int mp = w & 3;
            const int ng = (w >> 2) & 1;   // n-tiles ng*5..ng*5+4
            const int kh = w >> 3;         // k-steps kh*10..kh*10+9
            const unsigned aBase = uH + (mp*32 + l15)*688 + (lane>>4)*16 + kh*320;
            const unsigned bBase = uW2 + (ng*40 + l7)*688 + (l15>>3)*16 + kh*320;
            float acc2[2][5][4];
            #pragma unroll
            for (int mi = 0; mi < 2; mi++)
                #pragma unroll
                for (int j = 0; j < 5; j++)
                    #pragma unroll
                    for (int e = 0; e < 4; e++) acc2[mi][j][e] = 0.f;

            #pragma unroll
            for (int ks = 0; ks < 10; ks++) {
                unsigned a[2][4];
                ldsm_x4(a[0], aBase + ks*32);
                ldsm_x4(a[1], aBase + 16*688 + ks*32);
                #pragma unroll
                for (int j = 0; j < 5; j++) {
                    unsigned b0, b1;
                    ldsm_x2(b0, b1, bBase + j*5504 + ks*32);   // 8*688 = 5504
                    mma_bf16(acc2[0][j], a[0], b0, b1);
                    mma_bf16(acc2[1][j], a[1], b0, b1);
                }
            }
            __syncthreads();   // all warps done reading sH before alias overwrite
            float* sOut = kh ? sOutB : sOutA;
            #pragma unroll
            for (int mi = 0; mi < 2; mi++) {
                const int r0 = mp*32 + mi*16 + g;
                #pragma unroll
                for (int j = 0; j < 5; j++) {
                    const int c = (ng*5+j)*8 + 2*tq;
                    sOut[r0*81 + c]         = acc2[mi][j][0];
                    sOut[r0*81 + c + 1]     = acc2[mi][j][1];
                    sOut[(r0+8)*81 + c]     = acc2[mi][j][2];
                    sOut[(r0+8)*81 + c + 1] = acc2[mi][j][3];
                }
            }
        }
        __syncthreads();

        // ---- epilogue: reload x, out = x*inv + act(A+B+b2)*gamma ----
        {
            const int t = tid >> 2, lg = tid & 3;
            const float inv = sInv[t];
            const float4* xr = reinterpret_cast<const float4*>(xin + (tokBase + t)*80) + lg*5;
            float4* yr = reinterpret_cast<float4*>(xout + (tokBase + t)*80) + lg*5;
            #pragma unroll
            for (int u = 0; u < 5; u++) {
                float4 xf = xr[u];
                float xv[4] = {xf.x, xf.y, xf.z, xf.w};
                float f[4];
                #pragma unroll
                for (int e = 0; e < 4; e++) {
                    const int idx = lg*20 + 4*u + e;
                    float hv = sOutA[t*81 + idx] + sOutB[t*81 + idx] + sB2[idx];
                    if (RELU2) hv = fmaxf(hv, 0.f);
                    f[e] = xv[e]*inv + hv * sG[idx];
                }
                yr[u] = make_float4(f[0], f[1], f[2], f[3]);
            }
        }
        __syncthreads();   // before next supertile overwrites sXNh/sInv/sH
    }
}

// =====================================================================
extern "C" void kernel_launch(void* const* d_in, const int* in_sizes, int n_in,
                              void* d_out, int out_size)
{
    const float* x       = (const float*)d_in[0];
    const float* bw_qkv  = (const float*)d_in[1];
    const float* bb_qkv  = (const float*)d_in[2];
    const float* bw_proj = (const float*)d_in[3];
    const float* bb_proj = (const float*)d_in[4];
    const float* b_gamma = (const float*)d_in[5];
    const float* bw_mlp1 = (const float*)d_in[6];
    const float* bw_mlp2 = (const float*)d_in[7];
    const float* bb_mlp2 = (const float*)d_in[8];
    const float* gw_qkv  = (const float*)d_in[9];
    const float* gb_qkv  = (const float*)d_in[10];
    const float* gw_proj = (const float*)d_in[11];
    const float* gb_proj = (const float*)d_in[12];
    const float* g_gamma = (const float*)d_in[13];
    const float* gw_mlp1 = (const float*)d_in[14];
    const float* gw_mlp2 = (const float*)d_in[15];
    const float* gb_mlp2 = (const float*)d_in[16];
    float* out = (float*)d_out;

    float *buf1 = nullptr, *buf2 = nullptr;
    cudaGetSymbolAddress((void**)&buf1, g_buf1);
    cudaGetSymbolAddress((void**)&buf2, g_buf2);

    __nv_bfloat16 *qkvT_b, *projT_b, *qkvT_g, *projT_g, *w1T_b, *w2T_b, *w1T_g, *w2T_g;
    cudaGetSymbolAddress((void**)&qkvT_b,  g_qkvT_b);
    cudaGetSymbolAddress((void**)&projT_b, g_projT_b);
    cudaGetSymbolAddress((void**)&qkvT_g,  g_qkvT_g);
    cudaGetSymbolAddress((void**)&projT_g, g_projT_g);
    cudaGetSymbolAddress((void**)&w1T_b,   g_w1T_b);
    cudaGetSymbolAddress((void**)&w2T_b,   g_w2T_b);
    cudaGetSymbolAddress((void**)&w1T_g,   g_w1T_g);
    cudaGetSymbolAddress((void**)&w2T_g,   g_w2T_g);

    const size_t smA = ATTN_SMEM_BYTES;   // 156,160 B
    const size_t smM = MLP_SMEM_BYTES;    // 223,104 B
    cudaFuncSetAttribute(attn_kernel<false>, cudaFuncAttributeMaxDynamicSharedMemorySize, (int)smA);
    cudaFuncSetAttribute(attn_kernel<true>,  cudaFuncAttributeMaxDynamicSharedMemorySize, (int)smA);
    cudaFuncSetAttribute(mlp_kernel<true>,   cudaFuncAttributeMaxDynamicSharedMemorySize, (int)smM);
    cudaFuncSetAttribute(mlp_kernel<false>,  cudaFuncAttributeMaxDynamicSharedMemorySize, (int)smM);

    // ---- prepass: convert + transpose all weights to bf16 panels ----
    prep_kernel<<<32, 256>>>(bw_qkv,  qkvT_b,  80, 240, 88, 240);
    prep_kernel<<<32, 256>>>(bw_proj, projT_b, 80,  80, 88,  80);
    prep_kernel<<<32, 256>>>(gw_qkv,  qkvT_g,  80, 240, 88, 240);
    prep_kernel<<<32, 256>>>(gw_proj, projT_g, 80,  80, 88,  80);
    prep_kernel<<<32, 256>>>(bw_mlp1, w1T_b,   80, 320, 88, 320);
    prep_kernel<<<32, 256>>>(bw_mlp2, w2T_b,  320,  80, 344, 80);
    prep_kernel<<<32, 256>>>(gw_mlp1, w1T_g,   80, 320, 88, 320);
    prep_kernel<<<32, 256>>>(gw_mlp2, w2T_g,  320,  80, 344, 80);

    // stage 1: block SA
    attn_kernel<false><<<ATTN_NCTA, 256, smA>>>(x,    buf1, qkvT_b, bb_qkv, projT_b, bb_proj);
    mlp_kernel<true>  <<<MLP_NCTA,  512, smM>>>(buf1, buf2, w1T_b, w2T_b, bb_mlp2, b_gamma);
    // stage 2: grid SA
    attn_kernel<true> <<<ATTN_NCTA, 256, smA>>>(buf2, buf1, qkvT_g, gb_qkv, projT_g, gb_proj);
    mlp_kernel<false> <<<MLP_NCTA,  512, smM>>>(buf1, out, w1T_g, w2T_g, gb_mlp2, g_gamma);
}